// round 8
// baseline (speedup 1.0000x reference)
#include <cuda_runtime.h>
#include <cuda_bf16.h>

#define HDIM 1024
#define VDIM 50257
#define SDIM 4096
#define NCHUNK 256
#define CHUNK  (SDIM / NCHUNK)   // 16
#define NB 148
#define NT 1024

// ---------------- scratch (no allocations allowed) ----------------
__device__ float g_hnew[HDIM];
__device__ float g_context[HDIM];
__device__ float g_scores[SDIM];          // scores, then normalized attn in place
__device__ float g_gates[6 * HDIM];
__device__ float g_cpart[NCHUNK * HDIM];
__device__ float g_lse[1];
__device__ float2 g_pair[NB];
__device__ unsigned g_bar_count = 0;
__device__ unsigned g_bar_gen = 0;

// ---------------- helpers ----------------
__device__ __forceinline__ float warpSum(float v) {
#pragma unroll
    for (int o = 16; o > 0; o >>= 1) v += __shfl_xor_sync(0xffffffffu, v, o);
    return v;
}
__device__ __forceinline__ float warpMax(float v) {
#pragma unroll
    for (int o = 16; o > 0; o >>= 1) v = fmaxf(v, __shfl_xor_sync(0xffffffffu, v, o));
    return v;
}
__device__ __forceinline__ float dot4(float4 a, float4 b) {
    return a.x * b.x + a.y * b.y + a.z * b.z + a.w * b.w;
}

// software grid barrier: requires all blocks co-resident (grid == NB, 1 CTA/SM)
__device__ __forceinline__ void gridBarrier() {
    __threadfence();
    __syncthreads();
    if (threadIdx.x == 0) {
        unsigned gen = *((volatile unsigned*)&g_bar_gen);
        if (atomicAdd(&g_bar_count, 1u) == gridDim.x - 1) {
            g_bar_count = 0;
            __threadfence();
            atomicExch(&g_bar_gen, gen + 1);
        } else {
            while (*((volatile unsigned*)&g_bar_gen) == gen) { __nanosleep(64); }
        }
    }
    __syncthreads();
    __threadfence();
}

// ================= kernel 1: fused GRU + attention =================
__global__ __launch_bounds__(NT, 1) void k_pre(
    const int* __restrict__ word_input,
    const float* __restrict__ last_context,
    const float* __restrict__ last_hidden,
    const float* __restrict__ enc,
    const float* __restrict__ embedding,
    const float* __restrict__ w_ih,
    const float* __restrict__ w_hh,
    const float* __restrict__ b_ih,
    const float* __restrict__ b_hh,
    float* __restrict__ hnew_out,
    float* __restrict__ attn_out,
    float* __restrict__ ctx_out)
{
    __shared__ float smem[3 * HDIM];   // phase1: x(2048)+h(1024); phase3: h_new(1024)
    __shared__ float rb[32];
    __shared__ float bc[2];

    const int t = threadIdx.x, b = blockIdx.x;
    const int lane = t & 31, wp = t >> 5;
    const int gwarp = b * 32 + wp;          // 0..4735

    // ---- Phase 1: GRU gate dot products (warp per (gate,j)) ----
    {
        const int word = word_input[0];
        const float* erow = embedding + (size_t)word * HDIM;
        smem[t]            = erow[t];            // x[0:1024]  = emb
        smem[HDIM + t]     = last_context[t];    // x[1024:2048]
        smem[2 * HDIM + t] = last_hidden[t];     // h
        __syncthreads();
        const float4* x4 = (const float4*)smem;
        const float4* h4 = (const float4*)(smem + 2 * HDIM);

        for (int task = gwarp; task < 6 * HDIM; task += NB * 32) {
            const int g = task >> 10;
            const int j = task & (HDIM - 1);
            float acc = 0.f;
            if (g < 3) {
                const float4* w = (const float4*)(w_ih + (size_t)(g * HDIM + j) * (2 * HDIM));
#pragma unroll
                for (int i = 0; i < 16; i++) {
                    int idx = lane + 32 * i;
                    acc += dot4(__ldcs(&w[idx]), x4[idx]);
                }
            } else {
                const float4* w = (const float4*)(w_hh + (size_t)((g - 3) * HDIM + j) * HDIM);
#pragma unroll
                for (int i = 0; i < 8; i++) {
                    int idx = lane + 32 * i;
                    acc += dot4(__ldcs(&w[idx]), h4[idx]);
                }
            }
            acc = warpSum(acc);
            if (lane == 0) g_gates[task] = acc;
        }
    }
    gridBarrier();

    // ---- Phase 2: GRU nonlinearity (block 0) ----
    if (b == 0) {
        const int j = t;
        float gir = g_gates[j]            + b_ih[j];
        float giz = g_gates[j + HDIM]     + b_ih[j + HDIM];
        float gin = g_gates[j + 2 * HDIM] + b_ih[j + 2 * HDIM];
        float ghr = g_gates[j + 3 * HDIM] + b_hh[j];
        float ghz = g_gates[j + 4 * HDIM] + b_hh[j + HDIM];
        float ghn = g_gates[j + 5 * HDIM] + b_hh[j + 2 * HDIM];
        float r = 1.f / (1.f + expf(-(gir + ghr)));
        float z = 1.f / (1.f + expf(-(giz + ghz)));
        float n = tanhf(gin + r * ghn);
        float hn = (1.f - z) * n + z * smem[2 * HDIM + j];
        g_hnew[j] = hn;
        hnew_out[j] = hn;
    }
    gridBarrier();

    // ---- Phase 3: attention scores (warp per s row) ----
    {
        smem[t] = g_hnew[t];
        __syncthreads();
        const float4* h4 = (const float4*)smem;
        for (int s = gwarp; s < SDIM; s += NB * 32) {
            const float4* e4 = (const float4*)(enc + (size_t)s * HDIM);
            float acc = 0.f;
#pragma unroll
            for (int i = 0; i < 8; i++) {
                int idx = lane + 32 * i;
                acc += dot4(e4[idx], h4[idx]);
            }
            acc = warpSum(acc);
            if (lane == 0) g_scores[s] = acc;
        }
    }
    gridBarrier();

    // ---- Phase 4: softmax over S (block 0), normalize g_scores in place ----
    if (b == 0) {
        float v0 = g_scores[t];
        float v1 = g_scores[t + 1024];
        float v2 = g_scores[t + 2048];
        float v3 = g_scores[t + 3072];
        float m = fmaxf(fmaxf(v0, v1), fmaxf(v2, v3));
        m = warpMax(m);
        if (lane == 0) rb[wp] = m;
        __syncthreads();
        if (t < 32) {
            float x = warpMax(rb[t]);
            if (t == 0) bc[0] = x;
        }
        __syncthreads();
        const float M = bc[0];
        float e0 = expf(v0 - M), e1 = expf(v1 - M), e2 = expf(v2 - M), e3 = expf(v3 - M);
        float s = e0 + e1 + e2 + e3;
        s = warpSum(s);
        __syncthreads();
        if (lane == 0) rb[wp] = s;
        __syncthreads();
        if (t < 32) {
            float x = warpSum(rb[t]);
            if (t == 0) bc[1] = x;
        }
        __syncthreads();
        const float inv = 1.f / bc[1];
        e0 *= inv; e1 *= inv; e2 *= inv; e3 *= inv;
        g_scores[t]        = e0;  attn_out[t]        = e0;
        g_scores[t + 1024] = e1;  attn_out[t + 1024] = e1;
        g_scores[t + 2048] = e2;  attn_out[t + 2048] = e2;
        g_scores[t + 3072] = e3;  attn_out[t + 3072] = e3;
    }
    gridBarrier();

    // ---- Phase 5: context partials (block per S-chunk of 16, thread per col) ----
    for (int sc = b; sc < NCHUNK; sc += NB) {
        const int s0 = sc * CHUNK;
        const float* base = enc + (size_t)s0 * HDIM + t;
        float acc = 0.f;
#pragma unroll
        for (int s = 0; s < CHUNK; s++)
            acc += __ldg(&g_scores[s0 + s]) * base[(size_t)s * HDIM];
        g_cpart[sc * HDIM + t] = acc;
    }
    gridBarrier();

    // ---- Phase 6: context reduce (block 0) ----
    if (b == 0) {
        float acc = 0.f;
#pragma unroll
        for (int p = 0; p < NCHUNK; p++) acc += g_cpart[p * HDIM + t];
        g_context[t] = acc;
        ctx_out[t] = acc;
    }
}

// ================= kernel 2: output projection (dominant, 412 MB) =================
__global__ __launch_bounds__(256) void k_logits(const float* __restrict__ out_w,
                                                const float* __restrict__ out_b,
                                                float* __restrict__ logits)
{
    __shared__ float sy[2 * HDIM];
    const int t = threadIdx.x;
    for (int k = t; k < HDIM; k += 256) {
        sy[k]        = g_hnew[k];
        sy[HDIM + k] = g_context[k];
    }
    __syncthreads();
    const int lane = t & 31, w = t >> 5;
    const int r = blockIdx.x * 8 + w;
    if (r >= VDIM) return;
    const float4* w4 = (const float4*)(out_w + (size_t)r * (2 * HDIM));
    const float4* y4 = (const float4*)sy;
    float acc = 0.f;
#pragma unroll
    for (int i = lane; i < 512; i += 32)
        acc += dot4(__ldcs(&w4[i]), y4[i]);
    acc = warpSum(acc);
    if (lane == 0) logits[r] = acc + out_b[r];
}

// ================= kernel 3: fused log-sum-exp + subtract =================
__global__ __launch_bounds__(NT, 1) void k_post(float* __restrict__ out)
{
    __shared__ float rm[32], rs[32];
    const int t = threadIdx.x, b = blockIdx.x;
    const int lane = t & 31, wp = t >> 5;
    const int gtid = b * NT + t;
    const int stride = NB * NT;

    // per-thread online (m, s)
    float m = -1e30f, s = 0.f;
    for (int v = gtid; v < VDIM; v += stride) {
        float x = out[v];
        float M = fmaxf(m, x);
        s = s * expf(m - M) + expf(x - M);
        m = M;
    }
    // warp combine (fixed order)
#pragma unroll
    for (int o = 16; o > 0; o >>= 1) {
        float m2 = __shfl_xor_sync(0xffffffffu, m, o);
        float s2 = __shfl_xor_sync(0xffffffffu, s, o);
        float M = fmaxf(m, m2);
        s = s * expf(m - M) + s2 * expf(m2 - M);
        m = M;
    }
    if (lane == 0) { rm[wp] = m; rs[wp] = s; }
    __syncthreads();
    if (t == 0) {
        float M = rm[0], S = rs[0];
#pragma unroll
        for (int p = 1; p < 32; p++) {
            float M2 = fmaxf(M, rm[p]);
            S = S * expf(M - M2) + rs[p] * expf(rm[p] - M2);
            M = M2;
        }
        g_pair[b] = make_float2(M, S);
    }
    gridBarrier();
    if (b == 0 && t == 0) {
        float2 p0 = g_pair[0];
        float M = p0.x, S = p0.y;
        for (int p = 1; p < NB; p++) {
            float2 pp = g_pair[p];
            float M2 = fmaxf(M, pp.x);
            S = S * expf(M - M2) + pp.y * expf(pp.x - M2);
            M = M2;
        }
        g_lse[0] = M + logf(S);
    }
    gridBarrier();
    const float lse = g_lse[0];
    for (int v = gtid; v < VDIM; v += stride) out[v] -= lse;
}

// ---------------- launch ----------------
extern "C" void kernel_launch(void* const* d_in, const int* in_sizes, int n_in,
                              void* d_out, int out_size)
{
    const int*   word         = (const int*)d_in[0];
    const float* last_context = (const float*)d_in[1];
    const float* last_hidden  = (const float*)d_in[2];
    const float* enc          = (const float*)d_in[3];
    const float* embedding    = (const float*)d_in[4];
    const float* w_ih         = (const float*)d_in[5];
    const float* w_hh         = (const float*)d_in[6];
    const float* b_ih         = (const float*)d_in[7];
    const float* b_hh         = (const float*)d_in[8];
    const float* out_w        = (const float*)d_in[9];
    const float* out_b        = (const float*)d_in[10];

    float* out      = (float*)d_out;
    float* o_logits = out;                    // [V]   log_softmax output
    float* o_ctx    = out + VDIM;             // [H]   context
    float* o_hnew   = out + VDIM + HDIM;      // [H]   h_new
    float* o_attn   = out + VDIM + 2 * HDIM;  // [S]   attn

    k_pre<<<NB, NT>>>(word, last_context, last_hidden, enc, embedding,
                      w_ih, w_hh, b_ih, b_hh, o_hnew, o_attn, o_ctx);
    k_logits<<<(VDIM + 7) / 8, 256>>>(out_w, out_b, o_logits);
    k_post<<<NB, NT>>>(o_logits);
}